// round 4
// baseline (speedup 1.0000x reference)
#include <cuda_runtime.h>
#include <mma.h>
#include <math.h>

using namespace nvcuda;

#define NTOK 8192
#define DIM  384
#define NEXP 8
#define HID  1536
#define OUTD 384
#define NPAIR (NTOK * 2)

#define BM 128
#define BN 64
#define KC 32
#define LDA 40   // KC + 8 pad
#define LDB 72   // BN + 8 pad
#define LDO 72

// ---------------- device scratch ----------------
__device__ int    g_counts[NEXP];
__device__ int    g_list[NEXP * NTOK];
__device__ float2 g_gates[NTOK];
__device__ float  g_h[(size_t)NPAIR * HID];  // tf32-rounded activations

// ---------------- small kernels ----------------
__global__ void zero_counts_kernel() {
    if (threadIdx.x < NEXP) g_counts[threadIdx.x] = 0;
}

__global__ void zero_out_kernel(float* __restrict__ out) {
    int i = blockIdx.x * blockDim.x + threadIdx.x;
    if (i < NTOK * OUTD) out[i] = 0.f;
}

__global__ void router_kernel(const float* __restrict__ x,
                              const float* __restrict__ Wg,
                              const float* __restrict__ bg) {
    int warp = (blockIdx.x * blockDim.x + threadIdx.x) >> 5;
    int lane = threadIdx.x & 31;
    if (warp >= NTOK) return;

    const float* xr = x + (size_t)warp * DIM;
    float acc[NEXP];
#pragma unroll
    for (int e = 0; e < NEXP; e++) acc[e] = 0.f;

    for (int d = lane; d < DIM; d += 32) {
        float xv = xr[d];
        const float* wr = Wg + d * NEXP;
#pragma unroll
        for (int e = 0; e < NEXP; e++) acc[e] += xv * wr[e];
    }
#pragma unroll
    for (int e = 0; e < NEXP; e++) {
#pragma unroll
        for (int off = 16; off > 0; off >>= 1)
            acc[e] += __shfl_xor_sync(0xffffffffu, acc[e], off);
    }
    if (lane == 0) {
        float v0 = -1e30f, v1 = -1e30f;
        int   i0 = 0,      i1 = 0;
#pragma unroll
        for (int e = 0; e < NEXP; e++) {
            float v = acc[e] + bg[e];
            if (v > v0)      { v1 = v0; i1 = i0; v0 = v; i0 = e; }
            else if (v > v1) { v1 = v;  i1 = e; }
        }
        float e1 = expf(v1 - v0);
        float inv = 1.0f / (1.0f + e1);
        g_gates[warp] = make_float2(inv, e1 * inv);

        int p0 = atomicAdd(&g_counts[i0], 1);
        g_list[i0 * NTOK + p0] = warp * 2;
        int p1 = atomicAdd(&g_counts[i1], 1);
        g_list[i1 * NTOK + p1] = warp * 2 + 1;
    }
}

// ---------------- pipelined tf32 WMMA grouped GEMM ----------------
// G1:  h = gelu(gather(x) @ W1[e] + b1[e])        -> g_h (tf32-rounded)
// !G1: out[token] += gate * (gather(g_h) @ W2[e] + b2[e])   (atomic, 2 adds/elem)
template<bool G1>
__global__ __launch_bounds__(256, 2)
void gemm_kernel(const float* __restrict__ A,
                 const float* __restrict__ W,
                 const float* __restrict__ bias,
                 float* __restrict__ out) {
    const int e  = blockIdx.z;
    const int M  = g_counts[e];
    const int m0 = blockIdx.x * BM;
    if (m0 >= M) return;
    const int n0 = blockIdx.y * BN;
    const int Kd = G1 ? DIM : HID;
    const int Nd = G1 ? HID : OUTD;
    const int sa = G1 ? DIM : HID;   // A row stride

    __shared__ __align__(16) float smem[BM * LDO];  // 9216 floats, union w/ epilogue
    __shared__ int sEntry[BM];
    float* sA = smem;                 // BM*LDA = 5120
    float* sB = smem + BM * LDA;      // KC*LDB = 2304

    const int tid = threadIdx.x;
    if (tid < BM) {
        int r = m0 + tid;
        sEntry[tid] = (r < M) ? g_list[e * NTOK + r] : -1;
    }
    __syncthreads();

    const float* We = W + (size_t)e * Kd * Nd;

    wmma::fragment<wmma::accumulator, 16, 16, 8, float> c[2][2];
#pragma unroll
    for (int i = 0; i < 2; i++)
#pragma unroll
        for (int j = 0; j < 2; j++) wmma::fill_fragment(c[i][j], 0.f);

    const int w  = tid >> 5;
    const int wm = (w & 3) * 32;
    const int wn = (w >> 2) * 32;

    // load mapping: A chunk 128x32 as float4 (8 thr/row, 4 rows/thread)
    const int ar = tid >> 3;           // base row, +32*s
    const int ac = (tid & 7) * 4;      // col in chunk
    // B chunk 32x64 as float4 (16 thr/row, 2 slots/thread)
    const int br0 = tid >> 4,           bc0 = (tid & 15) * 4;
    const int br1 = (tid + 256) >> 4,   bc1 = bc0;

    float4 pa[4], pb[2];

    // ---- prefetch chunk 0 ----
#pragma unroll
    for (int s = 0; s < 4; s++) {
        int entry = sEntry[ar + 32 * s];
        pa[s] = (entry >= 0)
            ? *(const float4*)(A + (size_t)(G1 ? (entry >> 1) : entry) * sa + ac)
            : make_float4(0.f, 0.f, 0.f, 0.f);
    }
    pb[0] = *(const float4*)(We + (size_t)br0 * Nd + n0 + bc0);
    pb[1] = *(const float4*)(We + (size_t)br1 * Nd + n0 + bc1);

    const int nk = Kd / KC;
    for (int kc = 0; kc < nk; kc++) {
        // ---- commit prefetched chunk to smem (RNA tf32 conversion) ----
#pragma unroll
        for (int s = 0; s < 4; s++) {
            float* d = sA + (ar + 32 * s) * LDA + ac;
            d[0] = wmma::__float_to_tf32(pa[s].x);
            d[1] = wmma::__float_to_tf32(pa[s].y);
            d[2] = wmma::__float_to_tf32(pa[s].z);
            d[3] = wmma::__float_to_tf32(pa[s].w);
        }
        {
            float* d0 = sB + br0 * LDB + bc0;
            d0[0] = wmma::__float_to_tf32(pb[0].x);
            d0[1] = wmma::__float_to_tf32(pb[0].y);
            d0[2] = wmma::__float_to_tf32(pb[0].z);
            d0[3] = wmma::__float_to_tf32(pb[0].w);
            float* d1 = sB + br1 * LDB + bc1;
            d1[0] = wmma::__float_to_tf32(pb[1].x);
            d1[1] = wmma::__float_to_tf32(pb[1].y);
            d1[2] = wmma::__float_to_tf32(pb[1].z);
            d1[3] = wmma::__float_to_tf32(pb[1].w);
        }
        __syncthreads();

        // ---- prefetch chunk kc+1 (LDG overlaps MMA below) ----
        if (kc + 1 < nk) {
            const int k0 = (kc + 1) * KC;
#pragma unroll
            for (int s = 0; s < 4; s++) {
                int entry = sEntry[ar + 32 * s];
                pa[s] = (entry >= 0)
                    ? *(const float4*)(A + (size_t)(G1 ? (entry >> 1) : entry) * sa + k0 + ac)
                    : make_float4(0.f, 0.f, 0.f, 0.f);
            }
            pb[0] = *(const float4*)(We + (size_t)(k0 + br0) * Nd + n0 + bc0);
            pb[1] = *(const float4*)(We + (size_t)(k0 + br1) * Nd + n0 + bc1);
        }

        // ---- MMA on current chunk ----
#pragma unroll
        for (int ks = 0; ks < KC / 8; ks++) {
            wmma::fragment<wmma::matrix_a, 16, 16, 8, wmma::precision::tf32, wmma::row_major> a[2];
            wmma::fragment<wmma::matrix_b, 16, 16, 8, wmma::precision::tf32, wmma::row_major> b[2];
            wmma::load_matrix_sync(a[0], sA + wm * LDA + ks * 8, LDA);
            wmma::load_matrix_sync(a[1], sA + (wm + 16) * LDA + ks * 8, LDA);
            wmma::load_matrix_sync(b[0], sB + ks * 8 * LDB + wn, LDB);
            wmma::load_matrix_sync(b[1], sB + ks * 8 * LDB + wn + 16, LDB);
#pragma unroll
            for (int i = 0; i < 2; i++)
#pragma unroll
                for (int j = 0; j < 2; j++)
                    wmma::mma_sync(c[i][j], a[i], b[j], c[i][j]);
        }
        __syncthreads();
    }

    // ---- epilogue via smem ----
    float* sOut = smem;
#pragma unroll
    for (int i = 0; i < 2; i++)
#pragma unroll
        for (int j = 0; j < 2; j++)
            wmma::store_matrix_sync(sOut + (wm + i * 16) * LDO + wn + j * 16,
                                    c[i][j], LDO, wmma::mem_row_major);
    __syncthreads();

    if (G1) {
        const float* be = bias + e * HID;
        for (int idx = tid; idx < BM * BN; idx += 256) {
            int r = idx >> 6, cc = idx & 63;
            int entry = sEntry[r];
            if (entry >= 0) {
                float v = sOut[r * LDO + cc] + be[n0 + cc];
                float g = 0.5f * v * (1.0f + erff(v * 0.70710678118654752f));
                out[(size_t)entry * HID + n0 + cc] = wmma::__float_to_tf32(g);
            }
        }
    } else {
        const float* be = bias + e * OUTD;
        for (int idx = tid; idx < BM * BN; idx += 256) {
            int r = idx >> 6, cc = idx & 63;
            int entry = sEntry[r];
            if (entry >= 0) {
                float v = sOut[r * LDO + cc] + be[n0 + cc];
                int tok = entry >> 1;
                float2 gg = g_gates[tok];
                float gate = (entry & 1) ? gg.y : gg.x;
                atomicAdd(&out[(size_t)tok * OUTD + n0 + cc], v * gate);
            }
        }
    }
}

// ---------------- launch ----------------
extern "C" void kernel_launch(void* const* d_in, const int* in_sizes, int n_in,
                              void* d_out, int out_size) {
    const float* x  = (const float*)d_in[0];
    const float* Wg = (const float*)d_in[1];
    const float* bg = (const float*)d_in[2];
    const float* W1 = (const float*)d_in[3];
    const float* b1 = (const float*)d_in[4];
    const float* W2 = (const float*)d_in[5];
    const float* b2 = (const float*)d_in[6];
    float* out = (float*)d_out;

    zero_counts_kernel<<<1, 32>>>();
    router_kernel<<<(NTOK * 32) / 256, 256>>>(x, Wg, bg);
    zero_out_kernel<<<(NTOK * OUTD + 255) / 256, 256>>>(out);
    gemm_kernel<true><<<dim3(NTOK / BM, HID / BN, NEXP), 256>>>(x, W1, b1, g_h);
    gemm_kernel<false><<<dim3(NTOK / BM, OUTD / BN, NEXP), 256>>>(g_h, W2, b2, out);
}

// round 6
// speedup vs baseline: 6.5829x; 6.5829x over previous
#include <cuda_runtime.h>
#include <cstdint>
#include <mma.h>
#include <math.h>

using namespace nvcuda;

#define NTOK 8192
#define DIM  384
#define NEXP 8
#define HID  1536
#define OUTD 384
#define NPAIR (NTOK * 2)

#define BM 128
#define BN 64
#define KC 32
#define LDA 40   // KC + 8 pad (160B rows, 16B aligned)
#define LDB 72   // BN + 8 pad (288B rows, 16B aligned)
#define LDO 72

#define SA_SZ (BM * LDA)       // 5120 floats
#define SB_SZ (KC * LDB)       // 2304 floats
#define STAGE_SZ (SA_SZ + SB_SZ)
#define DSM_FLOATS (2 * STAGE_SZ)   // 14848 floats = 59392 B

// ---------------- device scratch ----------------
__device__ int    g_counts[NEXP];
__device__ int    g_list[NEXP * NTOK];
__device__ float2 g_gates[NTOK];
__device__ float  g_x [(size_t)NTOK * DIM];        // tf32-rounded x
__device__ float  g_w1[(size_t)NEXP * DIM * HID];  // tf32-rounded W1
__device__ float  g_w2[(size_t)NEXP * HID * OUTD]; // tf32-rounded W2
__device__ float  g_h [(size_t)NPAIR * HID];       // tf32-rounded activations

// ---------------- helpers ----------------
__device__ __forceinline__ void cp16(unsigned int smem_dst, const void* gsrc, int srcsize) {
    asm volatile("cp.async.cg.shared.global [%0], [%1], 16, %2;\n"
                 :: "r"(smem_dst), "l"(gsrc), "r"(srcsize) : "memory");
}
__device__ __forceinline__ void cp_commit() {
    asm volatile("cp.async.commit_group;\n" ::: "memory");
}
template<int N>
__device__ __forceinline__ void cp_wait() {
    asm volatile("cp.async.wait_group %0;\n" :: "n"(N) : "memory");
}

// ---------------- small kernels ----------------
__global__ void zero_counts_kernel() {
    if (threadIdx.x < NEXP) g_counts[threadIdx.x] = 0;
}

__global__ void zero_out_kernel(float* __restrict__ out) {
    int i = blockIdx.x * blockDim.x + threadIdx.x;
    if (i < NTOK * OUTD) out[i] = 0.f;
}

__global__ void round_tf32_kernel(const float* __restrict__ src,
                                  float* __restrict__ dst, int n4) {
    int i = blockIdx.x * blockDim.x + threadIdx.x;
    if (i >= n4) return;
    float4 v = ((const float4*)src)[i];
    v.x = wmma::__float_to_tf32(v.x);
    v.y = wmma::__float_to_tf32(v.y);
    v.z = wmma::__float_to_tf32(v.z);
    v.w = wmma::__float_to_tf32(v.w);
    ((float4*)dst)[i] = v;
}

__global__ void router_kernel(const float* __restrict__ x,
                              const float* __restrict__ Wg,
                              const float* __restrict__ bg) {
    int warp = (blockIdx.x * blockDim.x + threadIdx.x) >> 5;
    int lane = threadIdx.x & 31;
    if (warp >= NTOK) return;

    const float* xr = x + (size_t)warp * DIM;
    float acc[NEXP];
#pragma unroll
    for (int e = 0; e < NEXP; e++) acc[e] = 0.f;

    for (int d = lane; d < DIM; d += 32) {
        float xv = xr[d];
        const float* wr = Wg + d * NEXP;
#pragma unroll
        for (int e = 0; e < NEXP; e++) acc[e] += xv * wr[e];
    }
#pragma unroll
    for (int e = 0; e < NEXP; e++) {
#pragma unroll
        for (int off = 16; off > 0; off >>= 1)
            acc[e] += __shfl_xor_sync(0xffffffffu, acc[e], off);
    }
    if (lane == 0) {
        float v0 = -1e30f, v1 = -1e30f;
        int   i0 = 0,      i1 = 0;
#pragma unroll
        for (int e = 0; e < NEXP; e++) {
            float v = acc[e] + bg[e];
            if (v > v0)      { v1 = v0; i1 = i0; v0 = v; i0 = e; }
            else if (v > v1) { v1 = v;  i1 = e; }
        }
        float e1 = expf(v1 - v0);
        float inv = 1.0f / (1.0f + e1);
        g_gates[warp] = make_float2(inv, e1 * inv);

        int p0 = atomicAdd(&g_counts[i0], 1);
        g_list[i0 * NTOK + p0] = warp * 2;
        int p1 = atomicAdd(&g_counts[i1], 1);
        g_list[i1 * NTOK + p1] = warp * 2 + 1;
    }
}

// ---------------- cp.async double-buffered tf32 WMMA grouped GEMM ----------
// G1:  h = gelu(gather(g_x) @ g_w1[e] + b1[e])  -> g_h (tf32-rounded)
// !G1: out[token] += gate * (gather(g_h) @ g_w2[e] + b2[e])  (atomic)
template<bool G1>
__global__ __launch_bounds__(256)
void gemm_kernel(const float* __restrict__ A,
                 const float* __restrict__ W,
                 const float* __restrict__ bias,
                 float* __restrict__ out) {
    const int e  = blockIdx.z;
    const int M  = g_counts[e];
    const int m0 = blockIdx.x * BM;
    if (m0 >= M) return;
    const int n0 = blockIdx.y * BN;
    constexpr int Kd = G1 ? DIM : HID;
    constexpr int Nd = G1 ? HID : OUTD;
    constexpr int sa = G1 ? DIM : HID;
    constexpr int nk = Kd / KC;

    extern __shared__ __align__(16) float dsm[];
    __shared__ int sEntry[BM];

    const int tid = threadIdx.x;
    if (tid < BM) {
        int r = m0 + tid;
        sEntry[tid] = (r < M) ? g_list[e * NTOK + r] : -1;
    }
    __syncthreads();

    const float* We = W + (size_t)e * Kd * Nd;

    // load mapping
    const int ar = tid >> 3;            // A row base (0..31), +32*s
    const int ac = (tid & 7) * 4;       // A col (float4)
    const int br = tid >> 4;            // B row base (0..15), +16*s
    const int bc = (tid & 15) * 4;      // B col (float4)

    // A-row gmem pointers (valid fallback for masked rows)
    const float* aptr[4];
    int asz[4];
#pragma unroll
    for (int s = 0; s < 4; s++) {
        int entry = sEntry[ar + 32 * s];
        int row = entry < 0 ? 0 : (G1 ? (entry >> 1) : entry);
        aptr[s] = A + (size_t)row * sa + ac;
        asz[s] = entry < 0 ? 0 : 16;
    }

    unsigned int smem_u32 = (unsigned int)__cvta_generic_to_shared(dsm);

    // issue stage kc -> buffer (kc & 1)
    auto issue = [&](int kc) {
        unsigned int base = smem_u32 + (unsigned int)((kc & 1) * (STAGE_SZ * 4));
#pragma unroll
        for (int s = 0; s < 4; s++)
            cp16(base + (unsigned int)(((ar + 32 * s) * LDA + ac) * 4),
                 aptr[s] + kc * KC, asz[s]);
        unsigned int bbase = base + (unsigned int)(SA_SZ * 4);
        const float* wp = We + (size_t)kc * KC * Nd + n0 + bc;
#pragma unroll
        for (int s = 0; s < 2; s++)
            cp16(bbase + (unsigned int)(((br + 16 * s) * LDB + bc) * 4),
                 wp + (size_t)(br + 16 * s) * Nd, 16);
        cp_commit();
    };

    wmma::fragment<wmma::accumulator, 16, 16, 8, float> c[2][2];
#pragma unroll
    for (int i = 0; i < 2; i++)
#pragma unroll
        for (int j = 0; j < 2; j++) wmma::fill_fragment(c[i][j], 0.f);

    const int w  = tid >> 5;
    const int wm = (w & 3) * 32;
    const int wn = (w >> 2) * 32;

    issue(0);
    issue(1);

    for (int kc = 0; kc < nk; kc++) {
        if (kc == nk - 1) cp_wait<0>(); else cp_wait<1>();
        __syncthreads();

        const float* sA = dsm + (kc & 1) * STAGE_SZ;
        const float* sB = sA + SA_SZ;
#pragma unroll
        for (int ks = 0; ks < KC / 8; ks++) {
            wmma::fragment<wmma::matrix_a, 16, 16, 8, wmma::precision::tf32, wmma::row_major> a[2];
            wmma::fragment<wmma::matrix_b, 16, 16, 8, wmma::precision::tf32, wmma::row_major> b[2];
            wmma::load_matrix_sync(a[0], sA + wm * LDA + ks * 8, LDA);
            wmma::load_matrix_sync(a[1], sA + (wm + 16) * LDA + ks * 8, LDA);
            wmma::load_matrix_sync(b[0], sB + ks * 8 * LDB + wn, LDB);
            wmma::load_matrix_sync(b[1], sB + ks * 8 * LDB + wn + 16, LDB);
#pragma unroll
            for (int i = 0; i < 2; i++)
#pragma unroll
                for (int j = 0; j < 2; j++)
                    wmma::mma_sync(c[i][j], a[i], b[j], c[i][j]);
        }
        __syncthreads();
        if (kc + 2 < nk) issue(kc + 2);
    }

    // ---- epilogue via smem ----
    float* sOut = dsm;
#pragma unroll
    for (int i = 0; i < 2; i++)
#pragma unroll
        for (int j = 0; j < 2; j++)
            wmma::store_matrix_sync(sOut + (wm + i * 16) * LDO + wn + j * 16,
                                    c[i][j], LDO, wmma::mem_row_major);
    __syncthreads();

    if (G1) {
        const float* be = bias + e * HID;
        for (int idx = tid; idx < BM * BN; idx += 256) {
            int r = idx >> 6, cc = idx & 63;
            int entry = sEntry[r];
            if (entry >= 0) {
                float v = sOut[r * LDO + cc] + be[n0 + cc];
                float g = 0.5f * v * (1.0f + erff(v * 0.70710678118654752f));
                out[(size_t)entry * HID + n0 + cc] = wmma::__float_to_tf32(g);
            }
        }
    } else {
        const float* be = bias + e * OUTD;
        for (int idx = tid; idx < BM * BN; idx += 256) {
            int r = idx >> 6, cc = idx & 63;
            int entry = sEntry[r];
            if (entry >= 0) {
                float v = sOut[r * LDO + cc] + be[n0 + cc];
                int tok = entry >> 1;
                float2 gg = g_gates[tok];
                float gate = (entry & 1) ? gg.y : gg.x;
                atomicAdd(&out[(size_t)tok * OUTD + n0 + cc], v * gate);
            }
        }
    }
}

// ---------------- launch ----------------
extern "C" void kernel_launch(void* const* d_in, const int* in_sizes, int n_in,
                              void* d_out, int out_size) {
    const float* x  = (const float*)d_in[0];
    const float* Wg = (const float*)d_in[1];
    const float* bg = (const float*)d_in[2];
    const float* W1 = (const float*)d_in[3];
    const float* b1 = (const float*)d_in[4];
    const float* W2 = (const float*)d_in[5];
    const float* b2 = (const float*)d_in[6];
    float* out = (float*)d_out;

    static bool attr_done = false;
    if (!attr_done) {
        cudaFuncSetAttribute(gemm_kernel<true>,
                             cudaFuncAttributeMaxDynamicSharedMemorySize, DSM_FLOATS * 4);
        cudaFuncSetAttribute(gemm_kernel<false>,
                             cudaFuncAttributeMaxDynamicSharedMemorySize, DSM_FLOATS * 4);
        attr_done = true;
    }

    float *gx, *gw1, *gw2, *gh;
    cudaGetSymbolAddress((void**)&gx,  g_x);
    cudaGetSymbolAddress((void**)&gw1, g_w1);
    cudaGetSymbolAddress((void**)&gw2, g_w2);
    cudaGetSymbolAddress((void**)&gh,  g_h);

    zero_counts_kernel<<<1, 32>>>();
    router_kernel<<<(NTOK * 32) / 256, 256>>>(x, Wg, bg);
    zero_out_kernel<<<(NTOK * OUTD + 255) / 256, 256>>>(out);
    round_tf32_kernel<<<(NTOK * DIM / 4 + 255) / 256, 256>>>(x, gx, NTOK * DIM / 4);
    round_tf32_kernel<<<(NEXP * DIM * HID / 4 + 255) / 256, 256>>>(W1, gw1, NEXP * DIM * HID / 4);
    round_tf32_kernel<<<(NEXP * HID * OUTD / 4 + 255) / 256, 256>>>(W2, gw2, NEXP * HID * OUTD / 4);
    gemm_kernel<true><<<dim3(NTOK / BM, HID / BN, NEXP), 256, DSM_FLOATS * 4>>>(gx, gw1, b1, gh);
    gemm_kernel<false><<<dim3(NTOK / BM, OUTD / BN, NEXP), 256, DSM_FLOATS * 4>>>(gh, gw2, b2, out);
}